// round 16
// baseline (speedup 1.0000x reference)
#include <cuda_runtime.h>
#include <cstdint>
#include <math.h>

// Problem sizes (fixed per reference)
#define BROWS 32768
#define ND1   1024
#define ND2   4096

// ---------------- scratch (device globals; no allocations allowed) ----------------
// Fragment-major layouts:
//  g_At: [row/16][k/8] tiles of 128 floats, tile = lane-major float4
//  g_Bt: [n/8][k/16] tiles of 128 floats, tile = lane-major float4
__device__ float g_At[(size_t)BROWS * ND1];   // tf32-rounded g1 (fragment-major)
__device__ float g_Bt[(size_t)ND2 * ND1];     // tf32-rounded nW^T (fragment-major)
__device__ float g_invnc[ND2];
__device__ float g_pm[8 * BROWS];             // 4 qx * 2 nw partials
__device__ float g_ps[8 * BROWS];

static constexpr float LSE_SCALE = 14.426950408889634f;   // beta * log2(e), beta=10
static constexpr float OUT_SCALE = 0.069314718055994531f; // ln2 / beta

// ---------------- small helpers ----------------
__device__ __forceinline__ float tf32_rna(float x) {
    uint32_t r;
    asm("cvt.rna.tf32.f32 %0, %1;" : "=r"(r) : "f"(x));
    return __uint_as_float(r);
}

__device__ __forceinline__ float ex2(float x) {
    float y;
    asm("ex2.approx.f32 %0, %1;" : "=f"(y) : "f"(x));
    return y;
}

__device__ __forceinline__ uint32_t smem_to_u32(const void* smem_ptr) {
    uint32_t addr;
    asm("{ .reg .u64 tmp; cvta.to.shared.u64 tmp, %1; cvt.u32.u64 %0, tmp; }"
        : "=r"(addr) : "l"(smem_ptr));
    return addr;
}

__device__ __forceinline__ void cp_async16(uint32_t dst, const void* src) {
    asm volatile("cp.async.cg.shared.global [%0], [%1], 16;" :: "r"(dst), "l"(src));
}

__device__ __forceinline__ void mma_tf32(float* d, const uint32_t* a, const uint32_t* b) {
    asm volatile(
        "mma.sync.aligned.m16n8k8.row.col.f32.tf32.tf32.f32 "
        "{%0,%1,%2,%3}, {%4,%5,%6,%7}, {%8,%9}, {%0,%1,%2,%3};"
        : "+f"(d[0]), "+f"(d[1]), "+f"(d[2]), "+f"(d[3])
        : "r"(a[0]), "r"(a[1]), "r"(a[2]), "r"(a[3]), "r"(b[0]), "r"(b[1]));
}

#define MBAR_INIT(addr, cnt) \
    asm volatile("mbarrier.init.shared.b64 [%0], %1;" :: "r"(addr), "r"((uint32_t)(cnt)) : "memory")

#define MBAR_ARRIVE(addr) \
    asm volatile("{\n\t.reg .b64 t;\n\tmbarrier.arrive.shared.b64 t, [%0];\n\t}" \
                 :: "r"(addr) : "memory")

#define CPASYNC_MBAR_ARRIVE(addr) \
    asm volatile("cp.async.mbarrier.arrive.noinc.shared.b64 [%0];" :: "r"(addr) : "memory")

#define MBAR_WAIT_PAR(addr, par) do {                                        \
    asm volatile(                                                            \
        "{\n\t"                                                              \
        ".reg .pred P;\n\t"                                                  \
        "WAIT_%=:\n\t"                                                       \
        "mbarrier.try_wait.parity.shared.b64 P, [%0], %1;\n\t"               \
        "@!P bra WAIT_%=;\n\t"                                               \
        "}"                                                                  \
        :: "r"(addr), "r"((uint32_t)(par)) : "memory");                      \
} while (0)

// ---------------- GEMM constants ----------------
static constexpr int THREADS_G     = 256;
static constexpr int CHUNK_FLOATS  = 6144;                // A 4096 + B 2048 (24 KB, 16 k)
static constexpr int NSLOT         = 6;                   // depth 4 + skew 2
static constexpr int MB_OFF        = NSLOT * CHUNK_FLOATS * 4;  // 147456
static constexpr int SMEM_TOTAL    = MB_OFF + 96;         // 147552 B (1 CTA/SM)
static constexpr int NCHUNK_TOTAL  = 512;                 // 8 nt * 64 chunks

// ---------------- kernel 1: inverse column norms of W ----------------
__global__ void colnorm_kernel(const float* __restrict__ W) {
    __shared__ float red[256];
    const int tid = threadIdx.x;
    const int col = blockIdx.x * 32 + (tid & 31);
    const int seg = tid >> 5;             // 8 row segments of 128
    float s = 0.f;
    const int i0 = seg * 128;
    #pragma unroll 4
    for (int i = i0; i < i0 + 128; i++) {
        float v = W[(size_t)i * ND2 + col];
        s += v * v;
    }
    red[tid] = s;
    __syncthreads();
    if (tid < 32) {
        float t = red[tid];
        #pragma unroll
        for (int k = 1; k < 8; k++) t += red[tid + k * 32];
        g_invnc[blockIdx.x * 32 + tid] = rsqrtf(t);
    }
}

// ------- kernel 2: W -> normalized, transposed, 16-k fragment-major tf32 -------
__global__ void convertW_kernel(const float* __restrict__ W) {
    __shared__ float t[32 * 33];
    const int n0 = blockIdx.x * 32;
    const int k0 = blockIdx.y * 32;
    const int tx = threadIdx.x & 31;
    const int ty = threadIdx.x >> 5;      // 0..7 -> tile (k16 = ty>>2, nb = ty&3)
    #pragma unroll
    for (int r = ty; r < 32; r += 8)
        t[r * 33 + tx] = W[(size_t)(k0 + r) * ND2 + n0 + tx];   // t[k_l][n_l]
    __syncthreads();
    const int g = tx >> 2, tig = tx & 3;
    const int k16 = ty >> 2, nb = ty & 3;
    const int n_l = nb * 8 + g;
    const float inv = g_invnc[n0 + n_l];
    const int kb = k16 * 16;
    float4 o;
    o.x = tf32_rna(t[(kb + tig)      * 33 + n_l] * inv);
    o.y = tf32_rna(t[(kb + tig + 4)  * 33 + n_l] * inv);
    o.z = tf32_rna(t[(kb + tig + 8)  * 33 + n_l] * inv);
    o.w = tf32_rna(t[(kb + tig + 12) * 33 + n_l] * inv);
    *reinterpret_cast<float4*>(
        g_Bt + ((size_t)(n0 / 8 + nb) * (ND1 / 16) + k0 / 16 + k16) * 128 + tx * 4) = o;
}

// ------- kernel 3: g1 -> tf32-rounded, fragment-major -------
__global__ void convertA_kernel(const float* __restrict__ g1) {
    __shared__ float t[16 * 132];
    const int tid = threadIdx.x;
    const int rb = blockIdx.x;            // row block of 16
    const int kb0 = blockIdx.y * 16;      // 16 k-blocks of 8 (128 cols)
    const int r = tid >> 5;               // 0..7
    const int c4 = tid & 31;
    #pragma unroll
    for (int i = 0; i < 2; i++) {
        const float4 v = *reinterpret_cast<const float4*>(
            g1 + (size_t)(rb * 16 + r + i * 8) * ND1 + kb0 * 8 + c4 * 4);
        float* dst = t + (r + i * 8) * 132 + c4 * 4;
        dst[0] = tf32_rna(v.x); dst[1] = tf32_rna(v.y);
        dst[2] = tf32_rna(v.z); dst[3] = tf32_rna(v.w);
    }
    __syncthreads();
    const int lane = tid & 31;
    const int g = lane >> 2, tig = lane & 3;
    #pragma unroll
    for (int j = 0; j < 2; j++) {
        const int kb = (tid >> 5) + j * 8;   // 0..15
        float4 o;
        o.x = t[g * 132 + kb * 8 + tig];
        o.y = t[(g + 8) * 132 + kb * 8 + tig];
        o.z = t[g * 132 + kb * 8 + tig + 4];
        o.w = t[(g + 8) * 132 + kb * 8 + tig + 4];
        *reinterpret_cast<float4*>(
            g_At + ((size_t)rb * (ND1 / 8) + kb0 + kb) * 128 + lane * 4) = o;
    }
}

// ------- kernel 4: 256x128 tile, chunk-granular 6-slot mbarrier ring + LSE -------
__global__ void __launch_bounds__(THREADS_G, 1) gemm_lse_kernel() {
    extern __shared__ float smem[];
    const int tid  = threadIdx.x;
    const int wid  = tid >> 5;
    const int lane = tid & 31;
    const int g    = lane >> 2;
    const int tig  = lane & 3;
    const int mw   = wid & 3;      // 4 M-warps (64 rows each)
    const int nw   = wid >> 2;     // 2 N-warps (64 cols each)
    const int qx   = blockIdx.x;          // column quarter (1024 cols)
    const int row0 = blockIdx.y * 256;    // row block
    const uint32_t su = smem_to_u32(smem);
    const uint32_t mbF = su + MB_OFF;          // full[0..5], 8 B each
    const uint32_t mbE = su + MB_OFF + 48;     // empty[0..5]

    const int rb0 = row0 >> 4;            // global A row-block base (16 blocks)

    if (tid == 0) {
        #pragma unroll
        for (int s = 0; s < NSLOT; s++) {
            MBAR_INIT(mbF + s * 8, THREADS_G);
            MBAR_INIT(mbE + s * 8, THREADS_G);
        }
    }
    __syncthreads();

    // ---- fill indexing (thread-constant) ----
    // A chunk: 4096 floats -> 4 cp16/thread; B chunk: 2048 floats -> 2 cp16/thread
    const float* gA[4]; uint32_t dA[4];
    #pragma unroll
    for (int i = 0; i < 4; i++) {
        const int id = tid + i * 256;          // 0..1023
        const int rb = id >> 6, off = id & 63;
        gA[i] = g_At + (size_t)(rb0 + rb) * 16384 + (off >> 5) * 128 + (off & 31) * 4;
        dA[i] = (uint32_t)(rb * 256 + off * 4) * 4;
    }
    const float* gB[2]; uint32_t dB[2];
    #pragma unroll
    for (int i = 0; i < 2; i++) {
        const int id = tid + i * 256;          // 0..511
        const int nb = id >> 5, off = id & 31;
        gB[i] = g_Bt + (size_t)(qx * 128 + nb) * 8192 + off * 4;
        dB[i] = (uint32_t)(4096 + nb * 128 + off * 4) * 4;
    }

    // fragment base offsets (floats within a chunk)
    const int aFrag = mw * 4 * 256 + lane * 4;          // + mi*256 + ks*128
    const int bFrag = 4096 + nw * 8 * 128 + lane * 4;   // + ni*128

    float d[4][8][4];
    #pragma unroll
    for (int mi = 0; mi < 4; mi++)
        #pragma unroll
        for (int ni = 0; ni < 8; ni++)
            #pragma unroll
            for (int r = 0; r < 4; r++) d[mi][ni][r] = 0.f;

    // per-thread running LSE state
    float Mrun[2] = {-INFINITY, -INFINITY};
    float Srun[2] = {0.f, 0.f};

    // fill one chunk fc into slot; full-arrive deferred to cp.async completion
    auto fill = [&](int fc, int slot) {
        const uint32_t kA = (uint32_t)(fc & 63) << 8;    // A float offset (256/chunk)
        const uint32_t kB = ((uint32_t)(fc >> 6) << 17)  // nt stride (16 nb * 8192)
                          + ((uint32_t)(fc & 63) << 7);  // 128 floats/chunk per nb
        const uint32_t st = su + (uint32_t)slot * (CHUNK_FLOATS * 4);
        #pragma unroll
        for (int i = 0; i < 4; i++) cp_async16(st + dA[i], gA[i] + kA);
        #pragma unroll
        for (int i = 0; i < 2; i++) cp_async16(st + dB[i], gB[i] + kB);
        CPASYNC_MBAR_ARRIVE(mbF + slot * 8);
    };

    // prologue: chunks 0..3 into slots 0..3 (depth 4)
    #pragma unroll
    for (int p = 0; p < 4; p++) fill(p, p);

    int cs = 0; uint32_t cph = 0;                        // consumer slot / parity
    int fs = 4; uint32_t fph = 0; bool fneed = false;    // fill slot / parity

    for (int j = 0; j < NCHUNK_TOTAL; j++) {
        // fill chunk j+4 into slot fs; needs consumption of chunk j-2 (skew 2)
        if (j + 4 < NCHUNK_TOTAL) {
            if (fneed) MBAR_WAIT_PAR(mbE + fs * 8, fph);
            fill(j + 4, fs);
            if (++fs == NSLOT) { fs = 0; if (fneed) fph ^= 1; else fneed = true; }
        }

        MBAR_WAIT_PAR(mbF + cs * 8, cph);

        const float* C = smem + cs * CHUNK_FLOATS;
        // B fragments: 8 LDS.128, each holds both ks halves
        uint32_t b[8][4];
        #pragma unroll
        for (int ni = 0; ni < 8; ni++) {
            const float4 v = *reinterpret_cast<const float4*>(C + bFrag + ni * 128);
            b[ni][0] = __float_as_uint(v.x);
            b[ni][1] = __float_as_uint(v.y);
            b[ni][2] = __float_as_uint(v.z);
            b[ni][3] = __float_as_uint(v.w);
        }
        #pragma unroll
        for (int ks = 0; ks < 2; ks++) {
            float4 aq[4];
            #pragma unroll
            for (int mi = 0; mi < 4; mi++)
                aq[mi] = *reinterpret_cast<const float4*>(
                    C + aFrag + mi * 256 + ks * 128);
            #pragma unroll
            for (int ni = 0; ni < 8; ni++)
                #pragma unroll
                for (int mi = 0; mi < 4; mi++)
                    mma_tf32(d[mi][ni],
                             reinterpret_cast<const uint32_t*>(&aq[mi]),
                             &b[ni][ks * 2]);
        }
        MBAR_ARRIVE(mbE + cs * 8);
        if (++cs == NSLOT) { cs = 0; cph ^= 1; }

        if ((j & 63) == 63) {
            // ---- per-tile LSE fold (registers + quad shuffles, no syncthreads) ----
            #pragma unroll
            for (int cb = 0; cb < 8; cb++) {
                const int mi = cb >> 1, h = cb & 1;
                float v[16];
                float m = -INFINITY;
                #pragma unroll
                for (int ni = 0; ni < 8; ni++) {
                    v[ni * 2]     = d[mi][ni][h * 2]     * LSE_SCALE;
                    v[ni * 2 + 1] = d[mi][ni][h * 2 + 1] * LSE_SCALE;
                    m = fmaxf(m, fmaxf(v[ni * 2], v[ni * 2 + 1]));
                }
                float s = 0.f;
                #pragma unroll
                for (int t = 0; t < 16; t++) s += ex2(v[t] - m);
                #pragma unroll
                for (int off = 1; off <= 2; off <<= 1) {
                    const float om = __shfl_xor_sync(0xffffffffu, m, off);
                    const float os = __shfl_xor_sync(0xffffffffu, s, off);
                    const float nm = fmaxf(m, om);
                    s = s * ex2(m - nm) + os * ex2(om - nm);
                    m = nm;
                }
                if ((cb & 3) == tig) {
                    const int sl = cb >> 2;
                    const float nm = fmaxf(Mrun[sl], m);
                    Srun[sl] = Srun[sl] * ex2(Mrun[sl] - nm) + s * ex2(m - nm);
                    Mrun[sl] = nm;
                }
                #pragma unroll
                for (int ni = 0; ni < 8; ni++) {
                    d[mi][ni][h * 2] = 0.f;
                    d[mi][ni][h * 2 + 1] = 0.f;
                }
            }
        }
    }

    // write per-(qx,nw) partials; thread owns rows for cb=tig (slot0) and cb=tig+4 (slot1)
    {
        const int part = qx * 2 + nw;
        const int rloc = mw * 64 + (tig >> 1) * 16 + (tig & 1) * 8 + g;
        g_pm[(size_t)part * BROWS + row0 + rloc] = Mrun[0];
        g_ps[(size_t)part * BROWS + row0 + rloc] = Srun[0];
        g_pm[(size_t)part * BROWS + row0 + rloc + 32] = Mrun[1];
        g_ps[(size_t)part * BROWS + row0 + rloc + 32] = Srun[1];
    }
}

// ---------------- kernel 5: combine 8 partial LSEs per row ----------------
__global__ void combine_kernel(float* __restrict__ out) {
    const int row = blockIdx.x * blockDim.x + threadIdx.x;
    float ms[8];
    float M = -INFINITY;
    #pragma unroll
    for (int p = 0; p < 8; p++) {
        ms[p] = g_pm[(size_t)p * BROWS + row];
        M = fmaxf(M, ms[p]);
    }
    float S = 0.f;
    #pragma unroll
    for (int p = 0; p < 8; p++)
        S += g_ps[(size_t)p * BROWS + row] * ex2(ms[p] - M);
    out[row] = -(M + log2f(S)) * OUT_SCALE;
}

// ---------------- launch ----------------
extern "C" void kernel_launch(void* const* d_in, const int* in_sizes, int n_in,
                              void* d_out, int out_size) {
    const float* g1 = (const float*)d_in[0];
    const float* W  = (const float*)d_in[1];
    float* out = (float*)d_out;

    cudaFuncSetAttribute(gemm_lse_kernel,
                         cudaFuncAttributeMaxDynamicSharedMemorySize, SMEM_TOTAL);

    colnorm_kernel<<<ND2 / 32, 256>>>(W);
    convertW_kernel<<<dim3(ND2 / 32, ND1 / 32), dim3(256)>>>(W);
    convertA_kernel<<<dim3(BROWS / 16, ND1 / 128), 256>>>(g1);
    gemm_lse_kernel<<<dim3(4, BROWS / 256), THREADS_G, SMEM_TOTAL>>>();
    combine_kernel<<<BROWS / 256, 256>>>(out);
}

// round 17
// speedup vs baseline: 1.1143x; 1.1143x over previous
#include <cuda_runtime.h>
#include <cstdint>
#include <math.h>

// Problem sizes (fixed per reference)
#define BROWS 32768
#define ND1   1024
#define ND2   4096

// ---------------- scratch (device globals; no allocations allowed) ----------------
// Fragment-major layouts:
//  g_At: [row/16][k/8] tiles of 128 floats, tile = lane-major float4
//  g_Bt: [n/8][k/16] tiles of 128 floats, tile = lane-major float4
__device__ float g_At[(size_t)BROWS * ND1];   // tf32-rounded g1 (fragment-major)
__device__ float g_Bt[(size_t)ND2 * ND1];     // tf32-rounded nW^T (fragment-major)
__device__ float g_invnc[ND2];
__device__ float g_pm[32 * BROWS];            // 8 qx * 4 nw partials
__device__ float g_ps[32 * BROWS];

static constexpr float LSE_SCALE = 14.426950408889634f;   // beta * log2(e), beta=10
static constexpr float OUT_SCALE = 0.069314718055994531f; // ln2 / beta

// ---------------- small helpers ----------------
__device__ __forceinline__ float tf32_rna(float x) {
    uint32_t r;
    asm("cvt.rna.tf32.f32 %0, %1;" : "=r"(r) : "f"(x));
    return __uint_as_float(r);
}

__device__ __forceinline__ float ex2(float x) {
    float y;
    asm("ex2.approx.f32 %0, %1;" : "=f"(y) : "f"(x));
    return y;
}

__device__ __forceinline__ uint32_t smem_to_u32(const void* smem_ptr) {
    uint32_t addr;
    asm("{ .reg .u64 tmp; cvta.to.shared.u64 tmp, %1; cvt.u32.u64 %0, tmp; }"
        : "=r"(addr) : "l"(smem_ptr));
    return addr;
}

__device__ __forceinline__ void cp_async16(uint32_t dst, const void* src) {
    asm volatile("cp.async.cg.shared.global [%0], [%1], 16;" :: "r"(dst), "l"(src));
}

__device__ __forceinline__ void mma_tf32(float* d, const uint32_t* a, const uint32_t* b) {
    asm volatile(
        "mma.sync.aligned.m16n8k8.row.col.f32.tf32.tf32.f32 "
        "{%0,%1,%2,%3}, {%4,%5,%6,%7}, {%8,%9}, {%0,%1,%2,%3};"
        : "+f"(d[0]), "+f"(d[1]), "+f"(d[2]), "+f"(d[3])
        : "r"(a[0]), "r"(a[1]), "r"(a[2]), "r"(a[3]), "r"(b[0]), "r"(b[1]));
}

#define MBAR_INIT(addr, cnt) \
    asm volatile("mbarrier.init.shared.b64 [%0], %1;" :: "r"(addr), "r"((uint32_t)(cnt)) : "memory")

#define MBAR_ARRIVE(addr) \
    asm volatile("{\n\t.reg .b64 t;\n\tmbarrier.arrive.shared.b64 t, [%0];\n\t}" \
                 :: "r"(addr) : "memory")

#define CPASYNC_MBAR_ARRIVE(addr) \
    asm volatile("cp.async.mbarrier.arrive.noinc.shared.b64 [%0];" :: "r"(addr) : "memory")

#define MBAR_WAIT_PAR(addr, par) do {                                        \
    asm volatile(                                                            \
        "{\n\t"                                                              \
        ".reg .pred P;\n\t"                                                  \
        "WAIT_%=:\n\t"                                                       \
        "mbarrier.try_wait.parity.shared.b64 P, [%0], %1;\n\t"               \
        "@!P bra WAIT_%=;\n\t"                                               \
        "}"                                                                  \
        :: "r"(addr), "r"((uint32_t)(par)) : "memory");                      \
} while (0)

// ---------------- GEMM constants ----------------
static constexpr int THREADS_G    = 256;
static constexpr int CHUNK_FLOATS = 4096;                 // A 2048 + B 2048 (16 KB, 16 k)
static constexpr int SLOT_FLOATS  = 2 * CHUNK_FLOATS;     // pair slot (32 KB)
static constexpr int NSLOT        = 3;
static constexpr int RED_OFF      = NSLOT * SLOT_FLOATS;  // 24576 floats
static constexpr int MB_OFF       = (RED_OFF + 2 * 4 * 128) * 4;   // byte offset 102400
static constexpr int SMEM_TOTAL   = MB_OFF + 64;          // 102464 B
static constexpr int NPAIR_TOTAL  = 128;                  // 4 nt * 32 pairs per CTA

// ---------------- kernel 1: inverse column norms of W ----------------
__global__ void colnorm_kernel(const float* __restrict__ W) {
    __shared__ float red[256];
    const int tid = threadIdx.x;
    const int col = blockIdx.x * 32 + (tid & 31);
    const int seg = tid >> 5;             // 8 row segments of 128
    float s = 0.f;
    const int i0 = seg * 128;
    #pragma unroll 4
    for (int i = i0; i < i0 + 128; i++) {
        float v = W[(size_t)i * ND2 + col];
        s += v * v;
    }
    red[tid] = s;
    __syncthreads();
    if (tid < 32) {
        float t = red[tid];
        #pragma unroll
        for (int k = 1; k < 8; k++) t += red[tid + k * 32];
        g_invnc[blockIdx.x * 32 + tid] = rsqrtf(t);
    }
}

// ------- kernel 2: W -> normalized, transposed, 16-k fragment-major tf32 -------
__global__ void convertW_kernel(const float* __restrict__ W) {
    __shared__ float t[32 * 33];
    const int n0 = blockIdx.x * 32;
    const int k0 = blockIdx.y * 32;
    const int tx = threadIdx.x & 31;
    const int ty = threadIdx.x >> 5;      // 0..7 -> tile (k16 = ty>>2, nb = ty&3)
    #pragma unroll
    for (int r = ty; r < 32; r += 8)
        t[r * 33 + tx] = W[(size_t)(k0 + r) * ND2 + n0 + tx];   // t[k_l][n_l]
    __syncthreads();
    const int g = tx >> 2, tig = tx & 3;
    const int k16 = ty >> 2, nb = ty & 3;
    const int n_l = nb * 8 + g;
    const float inv = g_invnc[n0 + n_l];
    const int kb = k16 * 16;
    float4 o;
    o.x = tf32_rna(t[(kb + tig)      * 33 + n_l] * inv);
    o.y = tf32_rna(t[(kb + tig + 4)  * 33 + n_l] * inv);
    o.z = tf32_rna(t[(kb + tig + 8)  * 33 + n_l] * inv);
    o.w = tf32_rna(t[(kb + tig + 12) * 33 + n_l] * inv);
    *reinterpret_cast<float4*>(
        g_Bt + ((size_t)(n0 / 8 + nb) * (ND1 / 16) + k0 / 16 + k16) * 128 + tx * 4) = o;
}

// NOTE: g_Bt here is written as [n/8][k/16] tiles of 128 floats, but the GEMM
// consumes it as [n/8] slabs of 8192 floats with 16-k chunks of 128 floats —
// identical byte layout (k/16 tiles are consecutive within an n-block).

// ------- kernel 3: g1 -> tf32-rounded, fragment-major -------
__global__ void convertA_kernel(const float* __restrict__ g1) {
    __shared__ float t[16 * 132];
    const int tid = threadIdx.x;
    const int rb = blockIdx.x;            // row block of 16
    const int kb0 = blockIdx.y * 16;      // 16 k-blocks of 8 (128 cols)
    const int r = tid >> 5;               // 0..7
    const int c4 = tid & 31;
    #pragma unroll
    for (int i = 0; i < 2; i++) {
        const float4 v = *reinterpret_cast<const float4*>(
            g1 + (size_t)(rb * 16 + r + i * 8) * ND1 + kb0 * 8 + c4 * 4);
        float* dst = t + (r + i * 8) * 132 + c4 * 4;
        dst[0] = tf32_rna(v.x); dst[1] = tf32_rna(v.y);
        dst[2] = tf32_rna(v.z); dst[3] = tf32_rna(v.w);
    }
    __syncthreads();
    const int lane = tid & 31;
    const int g = lane >> 2, tig = lane & 3;
    #pragma unroll
    for (int j = 0; j < 2; j++) {
        const int kb = (tid >> 5) + j * 8;   // 0..15
        float4 o;
        o.x = t[g * 132 + kb * 8 + tig];
        o.y = t[(g + 8) * 132 + kb * 8 + tig];
        o.z = t[g * 132 + kb * 8 + tig + 4];
        o.w = t[(g + 8) * 132 + kb * 8 + tig + 4];
        *reinterpret_cast<float4*>(
            g_At + ((size_t)rb * (ND1 / 8) + kb0 + kb) * 128 + lane * 4) = o;
    }
}

// ---------------- kernel 4: mbarrier-pipelined tf32 GEMM + online LSE ----------------
__global__ void __launch_bounds__(THREADS_G, 2) gemm_lse_kernel() {
    extern __shared__ float smem[];
    const int tid  = threadIdx.x;
    const int wid  = tid >> 5;
    const int lane = tid & 31;
    const int g    = lane >> 2;
    const int tig  = lane & 3;
    const int mw   = wid & 1;      // 2 M-warps (64 rows each)
    const int nw   = wid >> 1;     // 4 N-warps (32 cols each)
    const int qx   = blockIdx.x;          // column eighth (512 cols, 4 nt)
    const int row0 = blockIdx.y * 128;    // row block
    const uint32_t su = smem_to_u32(smem);
    float* redm = smem + RED_OFF;         // [4][128]
    float* reds = redm + 4 * 128;
    const uint32_t mbF = su + MB_OFF;          // full[0..2], 8 B each
    const uint32_t mbE = su + MB_OFF + 24;     // empty[0..2]

    const int rb0 = row0 >> 4;            // global A row-block base

    if (tid == 0) {
        #pragma unroll
        for (int s = 0; s < NSLOT; s++) {
            MBAR_INIT(mbF + s * 8, THREADS_G);
            MBAR_INIT(mbE + s * 8, THREADS_G);
        }
    }
    __syncthreads();

    // ---- fill indexing (thread-constant) ----
    const int aarb = tid >> 6, aoff = tid & 63;       // A: rb aarb / aarb+4
    const int bnb  = tid >> 5, boff = tid & 31;       // B: nb bnb / bnb+8
    const uint32_t dA0 = (uint32_t)(aarb * 256 + aoff * 4) * 4;
    const uint32_t dA1 = (uint32_t)((aarb + 4) * 256 + aoff * 4) * 4;
    const uint32_t dB0 = (uint32_t)(2048 + bnb * 128 + boff * 4) * 4;
    const uint32_t dB1 = (uint32_t)(2048 + (bnb + 8) * 128 + boff * 4) * 4;
    const float* gA0 = g_At + (size_t)(rb0 + aarb) * 16384 + aoff * 4;
    const float* gA1 = gA0 + (size_t)4 * 16384;
    const float* gB0 = g_Bt + (size_t)(qx * 64 + bnb) * 8192 + boff * 4;
    const float* gB1 = gB0 + (size_t)8 * 8192;

    // fragment base offsets (floats within a chunk)
    const int aFrag = mw * 1024 + lane * 4;        // + mi*256 + ks*128
    const int bFrag = 2048 + nw * 512 + lane * 2;  // (unused path kept identical below)

    float d[4][4][4];
    #pragma unroll
    for (int mi = 0; mi < 4; mi++)
        #pragma unroll
        for (int ni = 0; ni < 4; ni++)
            #pragma unroll
            for (int r = 0; r < 4; r++) d[mi][ni][r] = 0.f;

    float mrun = -INFINITY, srun = 0.f;

    // R8 B-frag base (float4 per ni, both ks halves packed)
    const int bFrag4 = 2048 + nw * 512 + lane * 4; // + ni*128
    (void)bFrag;

    // fill one pair (2 chunks) for global pair fgp into slot; defer full-arrive
    auto fill = [&](int fgp, int slot) {
        const uint32_t kA = (uint32_t)(fgp & 31) << 9;                       // A float off
        const uint32_t kB = ((uint32_t)(fgp >> 5) << 17)
                          + ((uint32_t)(fgp & 31) << 8);                     // B float off
        const uint32_t st = su + (uint32_t)slot * (SLOT_FLOATS * 4);
        cp_async16(st + dA0, gA0 + kA);
        cp_async16(st + dA1, gA1 + kA);
        cp_async16(st + dB0, gB0 + kB);
        cp_async16(st + dB1, gB1 + kB);
        cp_async16(st + 16384 + dA0, gA0 + kA + 256);
        cp_async16(st + 16384 + dA1, gA1 + kA + 256);
        cp_async16(st + 16384 + dB0, gB0 + kB + 128);
        cp_async16(st + 16384 + dB1, gB1 + kB + 128);
        CPASYNC_MBAR_ARRIVE(mbF + slot * 8);
    };

    // prologue: fill all 3 slots (depth 3, R8 ordering)
    #pragma unroll
    for (int p = 0; p < NSLOT; p++) fill(p, p);

    int cs = 0, cph = 0;
    for (int gp = 0; gp < NPAIR_TOTAL; gp++) {
        const uint32_t mf = mbF + cs * 8;
        const uint32_t me = mbE + cs * 8;
        MBAR_WAIT_PAR(mf, cph);

        const float* S = smem + cs * SLOT_FLOATS;
        #pragma unroll
        for (int c = 0; c < 2; c++) {
            const float* C = S + c * CHUNK_FLOATS;
            uint32_t b[4][4];
            #pragma unroll
            for (int ni = 0; ni < 4; ni++) {
                const float4 v = *reinterpret_cast<const float4*>(C + bFrag4 + ni * 128);
                b[ni][0] = __float_as_uint(v.x);
                b[ni][1] = __float_as_uint(v.y);
                b[ni][2] = __float_as_uint(v.z);
                b[ni][3] = __float_as_uint(v.w);
            }
            #pragma unroll
            for (int ks = 0; ks < 2; ks++) {
                uint32_t a[4][4];
                #pragma unroll
                for (int mi = 0; mi < 4; mi++) {
                    const float4 v = *reinterpret_cast<const float4*>(
                        C + aFrag + mi * 256 + ks * 128);
                    a[mi][0] = __float_as_uint(v.x);
                    a[mi][1] = __float_as_uint(v.y);
                    a[mi][2] = __float_as_uint(v.z);
                    a[mi][3] = __float_as_uint(v.w);
                }
                #pragma unroll
                for (int ni = 0; ni < 4; ni++)
                    #pragma unroll
                    for (int mi = 0; mi < 4; mi++)
                        mma_tf32(d[mi][ni], a[mi], &b[ni][ks * 2]);
            }
        }
        MBAR_ARRIVE(me);

        // refill this slot 3 pairs ahead once every thread has consumed it
        if (gp < NPAIR_TOTAL - NSLOT) {
            MBAR_WAIT_PAR(me, cph);
            fill(gp + NSLOT, cs);
        }

        if (++cs == NSLOT) { cs = 0; cph ^= 1; }

        if ((gp & 31) == 31) {
            // ---- online LSE epilogue over this 128-col tile ----
            #pragma unroll
            for (int mi = 0; mi < 4; mi++) {
                #pragma unroll
                for (int h = 0; h < 2; h++) {
                    float v[8];
                    float m = -INFINITY;
                    #pragma unroll
                    for (int ni = 0; ni < 4; ni++) {
                        v[ni * 2]     = d[mi][ni][h * 2]     * LSE_SCALE;
                        v[ni * 2 + 1] = d[mi][ni][h * 2 + 1] * LSE_SCALE;
                        m = fmaxf(m, fmaxf(v[ni * 2], v[ni * 2 + 1]));
                    }
                    float s = 0.f;
                    #pragma unroll
                    for (int jj = 0; jj < 8; jj++) s += ex2(v[jj] - m);
                    #pragma unroll
                    for (int off = 1; off <= 2; off <<= 1) {
                        const float om = __shfl_xor_sync(0xffffffffu, m, off);
                        const float os = __shfl_xor_sync(0xffffffffu, s, off);
                        const float nm = fmaxf(m, om);
                        s = s * ex2(m - nm) + os * ex2(om - nm);
                        m = nm;
                    }
                    if (tig == 0) {
                        const int lr = mw * 64 + mi * 16 + h * 8 + g;
                        redm[nw * 128 + lr] = m;
                        reds[nw * 128 + lr] = s;
                    }
                }
            }
            __syncthreads();
            if (tid < 128) {
                #pragma unroll
                for (int w = 0; w < 4; w++) {
                    const float m = redm[w * 128 + tid];
                    const float s = reds[w * 128 + tid];
                    const float nm = fmaxf(mrun, m);
                    srun = srun * ex2(mrun - nm) + s * ex2(m - nm);
                    mrun = nm;
                }
            }
            __syncthreads();
            #pragma unroll
            for (int mi = 0; mi < 4; mi++)
                #pragma unroll
                for (int ni = 0; ni < 4; ni++)
                    #pragma unroll
                    for (int r = 0; r < 4; r++) d[mi][ni][r] = 0.f;
        }
    }

    if (tid < 128) {
        const int part = qx;   // one partial per CTA per row (cross-nw folded in smem)
        g_pm[(size_t)(part * 4) * BROWS + row0 + tid] = mrun;   // keep stride-4 slots
        g_ps[(size_t)(part * 4) * BROWS + row0 + tid] = srun;
        // unused nw slots (part*4+1..3) are never written; combine skips them
    }
}

// ---------------- kernel 5: combine 8 partial LSEs per row ----------------
__global__ void combine_kernel(float* __restrict__ out) {
    const int row = blockIdx.x * blockDim.x + threadIdx.x;
    float ms[8];
    float M = -INFINITY;
    #pragma unroll
    for (int p = 0; p < 8; p++) {
        ms[p] = g_pm[(size_t)(p * 4) * BROWS + row];
        M = fmaxf(M, ms[p]);
    }
    float S = 0.f;
    #pragma unroll
    for (int p = 0; p < 8; p++)
        S += g_ps[(size_t)(p * 4) * BROWS + row] * ex2(ms[p] - M);
    out[row] = -(M + log2f(S)) * OUT_SCALE;
}

// ---------------- launch ----------------
extern "C" void kernel_launch(void* const* d_in, const int* in_sizes, int n_in,
                              void* d_out, int out_size) {
    const float* g1 = (const float*)d_in[0];
    const float* W  = (const float*)d_in[1];
    float* out = (float*)d_out;

    cudaFuncSetAttribute(gemm_lse_kernel,
                         cudaFuncAttributeMaxDynamicSharedMemorySize, SMEM_TOTAL);

    colnorm_kernel<<<ND2 / 32, 256>>>(W);
    convertW_kernel<<<dim3(ND2 / 32, ND1 / 32), dim3(256)>>>(W);
    convertA_kernel<<<dim3(BROWS / 16, ND1 / 128), 256>>>(g1);
    gemm_lse_kernel<<<dim3(8, BROWS / 128), THREADS_G, SMEM_TOTAL>>>();
    combine_kernel<<<BROWS / 256, 256>>>(out);
}